// round 10
// baseline (speedup 1.0000x reference)
#include <cuda_runtime.h>

// GAE backward scan, round 10: R9 + chunk-MINOR ticket mapping.
// adv[t] = delta[t] + GL*adv[t+1],  delta[t] = r[t] + GAMMA*v[t+1] - v[t]
// Mapping k = ticket&31, gx = ticket>>5 puts a column-group's whole 32-chunk
// dependency chain on consecutive tickets -> all co-resident (740 CTA slots),
// so lookback flag-waits collapse to ~0 (previous chunk-major mapping put each
// block exactly at the edge of the 6-chunk dependency window).
// Single graph node: monotonic epoch flags, no reset kernel.

#define B_COLS 32768
#define TM1 1023            // output rows t = 0 .. 1022
#define GAMMA 0.99f
#define GL (0.99f * 0.95f)
#define NCHUNK 32
#define RMAX 32             // rows per chunk (last chunk: 31 valid)
#define GBLK 128            // column groups of 256 columns (B_COLS / 256)
#define NBLK (NCHUNK * GBLK)   // 4096
#define DEPTH 6             // gl^(32*6) ~ 7.7e-6 << 1e-3 tolerance

__device__ float g_scratch[NCHUNK * B_COLS];    // C_k per (chunk, column)
__device__ unsigned int g_flags[NCHUNK * GBLK]; // epoch-stamped flags (zero-init)
__device__ unsigned int g_ticket;               // monotonic across replays

__global__ __launch_bounds__(128, 5) void gae_chunk_kernel(
    const float* __restrict__ rewards,
    const float* __restrict__ values,
    float* __restrict__ out)
{
    __shared__ unsigned int s_ticket;
    if (threadIdx.x == 0) s_ticket = atomicAdd(&g_ticket, 1u);
    __syncthreads();
    const unsigned int ticket = s_ticket;
    const unsigned int want = (ticket >> 12) + 1u;   // epoch + 1
    const unsigned int lt = ticket & (NBLK - 1);
    const int k  = (int)(lt & (NCHUNK - 1));  // chunk index 0..31 (minor!)
    const int gx = (int)(lt >> 5);            // column group 0..127 (major)
    const int c2 = gx * 128 + threadIdx.x;    // float2 column index (0..16383)
    const int ROW2 = B_COLS / 2;              // row stride in float2 units
    const int t_hi = (TM1 - 1) - RMAX * k;    // 1022 - 32k

    const float2* r = (const float2*)rewards + c2;
    const float2* v = (const float2*)values + c2;
    float2* o = (float2*)out + c2;

    // ---- local backward scan (carry-in = 0), 32 rows, batched LDG.64 ----
    float2 local[RMAX];
    float ax = 0.0f, ay = 0.0f;
    float2 vn = __ldcs(v + (t_hi + 1) * ROW2);

    if (k < NCHUNK - 1) {
        // Fast path: all rows valid, no predication.
        #pragma unroll
        for (int g0 = 0; g0 < RMAX; g0 += 8) {
            float2 rt[8], vt[8];
            #pragma unroll
            for (int i = 0; i < 8; ++i) {
                const int t = t_hi - (g0 + i);
                rt[i] = __ldcs(r + t * ROW2);
                vt[i] = __ldcs(v + t * ROW2);
            }
            #pragma unroll
            for (int i = 0; i < 8; ++i) {
                const float dx = fmaf(GAMMA, vn.x, rt[i].x) - vt[i].x;
                const float dy = fmaf(GAMMA, vn.y, rt[i].y) - vt[i].y;
                ax = fmaf(GL, ax, dx);
                ay = fmaf(GL, ay, dy);
                local[g0 + i] = make_float2(ax, ay);
                vn = vt[i];
            }
        }
        // publish chunk-sum C_k with epoch stamp
        *(float2*)&g_scratch[k * B_COLS + 2 * c2] = local[RMAX - 1];
        __threadfence();
        __syncthreads();
        if (threadIdx.x == 0) atomicExch(&g_flags[k * GBLK + gx], want);
    } else {
        // Last chunk (k=31): t goes 30..0; row index 31 invalid. No consumers.
        #pragma unroll
        for (int g0 = 0; g0 < RMAX; g0 += 8) {
            float2 rt[8], vt[8];
            #pragma unroll
            for (int i = 0; i < 8; ++i) {
                const int t = t_hi - (g0 + i);
                if (t >= 0) {
                    rt[i] = __ldcs(r + t * ROW2);
                    vt[i] = __ldcs(v + t * ROW2);
                } else {
                    rt[i] = make_float2(0.0f, 0.0f);
                    vt[i] = make_float2(0.0f, 0.0f);
                }
            }
            #pragma unroll
            for (int i = 0; i < 8; ++i) {
                const float dx = fmaf(GAMMA, vn.x, rt[i].x) - vt[i].x;
                const float dy = fmaf(GAMMA, vn.y, rt[i].y) - vt[i].y;
                ax = fmaf(GL, ax, dx);
                ay = fmaf(GL, ay, dy);
                local[g0 + i] = make_float2(ax, ay);
                vn = vt[i];
            }
        }
    }

    // ---- truncated lookback: A = sum_{j=k-1 .. k-d} C_j * gl^(32*(k-1-j)) ----
    float Ax = 0.0f, Ay = 0.0f;
    if (k > 0) {
        const int d = (k < DEPTH) ? k : DEPTH;
        if (threadIdx.x < (unsigned)d) {  // thread i waits on predecessor (k-1-i)
            unsigned int* fp = &g_flags[(k - 1 - (int)threadIdx.x) * GBLK + gx];
            while (atomicAdd(fp, 0u) < want) {}
        }
        __syncthreads();

        // gl^32 via 5 squarings
        const float g2 = GL * GL, g4 = g2 * g2, g8 = g4 * g4;
        const float g16 = g8 * g8, gl32 = g16 * g16;

        float w = 1.0f;
        for (int j = k - 1; j >= k - d; --j) {
            const float2 Cj = *(const float2*)&g_scratch[j * B_COLS + 2 * c2];
            Ax = fmaf(Cj.x, w, Ax);
            Ay = fmaf(Cj.y, w, Ay);
            w *= gl32;
        }
    }

    // ---- fixup + store: adv[t_hi - i] = local[i] + A * gl^(i+1) ----
    if (k < NCHUNK - 1) {
        #pragma unroll
        for (int i = 0; i < RMAX; ++i) {
            Ax *= GL;
            Ay *= GL;
            __stcs(o + (t_hi - i) * ROW2,
                   make_float2(local[i].x + Ax, local[i].y + Ay));
        }
    } else {
        #pragma unroll
        for (int i = 0; i < RMAX; ++i) {
            const int t = t_hi - i;
            Ax *= GL;
            Ay *= GL;
            if (t >= 0)
                __stcs(o + t * ROW2,
                       make_float2(local[i].x + Ax, local[i].y + Ay));
        }
    }
}

extern "C" void kernel_launch(void* const* d_in, const int* in_sizes, int n_in,
                              void* d_out, int out_size) {
    const float* rewards = (const float*)d_in[0];
    const float* values  = (const float*)d_in[1];
    float* out = (float*)d_out;

    gae_chunk_kernel<<<NBLK, 128>>>(rewards, values, out);
}

// round 11
// speedup vs baseline: 1.1142x; 1.1142x over previous
#include <cuda_runtime.h>

// GAE backward scan, round 11: R9 (chunk-major, epoch flags, single graph node,
// 5 blocks/SM reg budget) with HALF-SIZE tiles to shrink the end-of-kernel
// straggler tail, and DEPTH 6->5.
// adv[t] = delta[t] + GL*adv[t+1],  delta[t] = r[t] + GAMMA*v[t+1] - v[t]
// Tiles: 32 rows x 128 columns (64 float2) per 64-thread block; 8192 tiles.
// Per-SM thread count unchanged (10 blocks x 64 thr = 640); tile duration
// halves -> tail idle roughly halves.

#define B_COLS 32768
#define TM1 1023            // output rows t = 0 .. 1022
#define GAMMA 0.99f
#define GL (0.99f * 0.95f)
#define NCHUNK 32
#define RMAX 32             // rows per chunk (last chunk: 31 valid)
#define GBLK 256            // column groups of 128 columns (B_COLS / 128)
#define NBLK (NCHUNK * GBLK)   // 8192
#define TPB 64              // threads per block (64 float2 columns per tile)
#define DEPTH 5             // gl^(32*5) ~ 5.5e-5 << 1e-3 tolerance

__device__ float g_scratch[NCHUNK * B_COLS];    // C_k per (chunk, column)
__device__ unsigned int g_flags[NCHUNK * GBLK]; // epoch-stamped flags (zero-init)
__device__ unsigned int g_ticket;               // monotonic across replays

__global__ __launch_bounds__(TPB, 10) void gae_chunk_kernel(
    const float* __restrict__ rewards,
    const float* __restrict__ values,
    float* __restrict__ out)
{
    __shared__ unsigned int s_ticket;
    if (threadIdx.x == 0) s_ticket = atomicAdd(&g_ticket, 1u);
    __syncthreads();
    const unsigned int ticket = s_ticket;
    const unsigned int want = (ticket >> 13) + 1u;   // epoch + 1 (NBLK = 8192)
    const unsigned int lt = ticket & (NBLK - 1);
    const int k  = (int)(lt >> 8);            // chunk index 0..31 (major)
    const int gx = (int)(lt & (GBLK - 1));    // column group 0..255
    const int c2 = gx * TPB + threadIdx.x;    // float2 column index (0..16383)
    const int ROW2 = B_COLS / 2;              // row stride in float2 units
    const int t_hi = (TM1 - 1) - RMAX * k;    // 1022 - 32k

    const float2* r = (const float2*)rewards + c2;
    const float2* v = (const float2*)values + c2;
    float2* o = (float2*)out + c2;

    // ---- local backward scan (carry-in = 0), 32 rows, batched LDG.64 ----
    float2 local[RMAX];
    float ax = 0.0f, ay = 0.0f;
    float2 vn = __ldcs(v + (t_hi + 1) * ROW2);

    if (k < NCHUNK - 1) {
        // Fast path: all rows valid, no predication.
        #pragma unroll
        for (int g0 = 0; g0 < RMAX; g0 += 8) {
            float2 rt[8], vt[8];
            #pragma unroll
            for (int i = 0; i < 8; ++i) {
                const int t = t_hi - (g0 + i);
                rt[i] = __ldcs(r + t * ROW2);
                vt[i] = __ldcs(v + t * ROW2);
            }
            #pragma unroll
            for (int i = 0; i < 8; ++i) {
                const float dx = fmaf(GAMMA, vn.x, rt[i].x) - vt[i].x;
                const float dy = fmaf(GAMMA, vn.y, rt[i].y) - vt[i].y;
                ax = fmaf(GL, ax, dx);
                ay = fmaf(GL, ay, dy);
                local[g0 + i] = make_float2(ax, ay);
                vn = vt[i];
            }
        }
        // publish chunk-sum C_k with epoch stamp
        *(float2*)&g_scratch[k * B_COLS + 2 * c2] = local[RMAX - 1];
        __threadfence();
        __syncthreads();
        if (threadIdx.x == 0) atomicExch(&g_flags[k * GBLK + gx], want);
    } else {
        // Last chunk (k=31): t goes 30..0; row index 31 invalid. No consumers.
        #pragma unroll
        for (int g0 = 0; g0 < RMAX; g0 += 8) {
            float2 rt[8], vt[8];
            #pragma unroll
            for (int i = 0; i < 8; ++i) {
                const int t = t_hi - (g0 + i);
                if (t >= 0) {
                    rt[i] = __ldcs(r + t * ROW2);
                    vt[i] = __ldcs(v + t * ROW2);
                } else {
                    rt[i] = make_float2(0.0f, 0.0f);
                    vt[i] = make_float2(0.0f, 0.0f);
                }
            }
            #pragma unroll
            for (int i = 0; i < 8; ++i) {
                const float dx = fmaf(GAMMA, vn.x, rt[i].x) - vt[i].x;
                const float dy = fmaf(GAMMA, vn.y, rt[i].y) - vt[i].y;
                ax = fmaf(GL, ax, dx);
                ay = fmaf(GL, ay, dy);
                local[g0 + i] = make_float2(ax, ay);
                vn = vt[i];
            }
        }
    }

    // ---- truncated lookback: A = sum_{j=k-1 .. k-d} C_j * gl^(32*(k-1-j)) ----
    float Ax = 0.0f, Ay = 0.0f;
    if (k > 0) {
        const int d = (k < DEPTH) ? k : DEPTH;
        if (threadIdx.x < (unsigned)d) {  // thread i waits on predecessor (k-1-i)
            unsigned int* fp = &g_flags[(k - 1 - (int)threadIdx.x) * GBLK + gx];
            while (atomicAdd(fp, 0u) < want) {}
        }
        __syncthreads();

        // gl^32 via 5 squarings
        const float g2 = GL * GL, g4 = g2 * g2, g8 = g4 * g4;
        const float g16 = g8 * g8, gl32 = g16 * g16;

        float w = 1.0f;
        for (int j = k - 1; j >= k - d; --j) {
            const float2 Cj = *(const float2*)&g_scratch[j * B_COLS + 2 * c2];
            Ax = fmaf(Cj.x, w, Ax);
            Ay = fmaf(Cj.y, w, Ay);
            w *= gl32;
        }
    }

    // ---- fixup + store: adv[t_hi - i] = local[i] + A * gl^(i+1) ----
    if (k < NCHUNK - 1) {
        #pragma unroll
        for (int i = 0; i < RMAX; ++i) {
            Ax *= GL;
            Ay *= GL;
            __stcs(o + (t_hi - i) * ROW2,
                   make_float2(local[i].x + Ax, local[i].y + Ay));
        }
    } else {
        #pragma unroll
        for (int i = 0; i < RMAX; ++i) {
            const int t = t_hi - i;
            Ax *= GL;
            Ay *= GL;
            if (t >= 0)
                __stcs(o + t * ROW2,
                       make_float2(local[i].x + Ax, local[i].y + Ay));
        }
    }
}

extern "C" void kernel_launch(void* const* d_in, const int* in_sizes, int n_in,
                              void* d_out, int out_size) {
    const float* rewards = (const float*)d_in[0];
    const float* values  = (const float*)d_in[1];
    float* out = (float*)d_out;

    gae_chunk_kernel<<<NBLK, TPB>>>(rewards, values, out);
}

// round 12
// speedup vs baseline: 1.1488x; 1.0310x over previous
#include <cuda_runtime.h>

// GAE backward scan, round 12: R11 with warp-sized tiles (TPB=32).
// adv[t] = delta[t] + GL*adv[t+1],  delta[t] = r[t] + GAMMA*v[t+1] - v[t]
// Tiles: 32 rows x 64 columns (32 float2) per 32-thread block; 16384 tiles.
// 20 blocks/SM x 32 thr = 640 threads/SM (same latency hiding as R11); tile
// duration halves again -> straggler tail shrinks further. Single graph node
// via monotonic epoch flags; chunk-major order (R10 proved coherence matters).

#define B_COLS 32768
#define TM1 1023            // output rows t = 0 .. 1022
#define GAMMA 0.99f
#define GL (0.99f * 0.95f)
#define NCHUNK 32
#define RMAX 32             // rows per chunk (last chunk: 31 valid)
#define GBLK 512            // column groups of 64 columns (B_COLS / 64)
#define NBLK (NCHUNK * GBLK)   // 16384
#define TPB 32              // threads per block (32 float2 columns per tile)
#define DEPTH 5             // gl^(32*5) ~ 5.5e-5 << 1e-3 tolerance

__device__ float g_scratch[NCHUNK * B_COLS];    // C_k per (chunk, column)
__device__ unsigned int g_flags[NCHUNK * GBLK]; // epoch-stamped flags (zero-init)
__device__ unsigned int g_ticket;               // monotonic across replays

__global__ __launch_bounds__(TPB, 20) void gae_chunk_kernel(
    const float* __restrict__ rewards,
    const float* __restrict__ values,
    float* __restrict__ out)
{
    __shared__ unsigned int s_ticket;
    if (threadIdx.x == 0) s_ticket = atomicAdd(&g_ticket, 1u);
    __syncthreads();
    const unsigned int ticket = s_ticket;
    const unsigned int want = (ticket >> 14) + 1u;   // epoch + 1 (NBLK = 16384)
    const unsigned int lt = ticket & (NBLK - 1);
    const int k  = (int)(lt >> 9);            // chunk index 0..31 (major)
    const int gx = (int)(lt & (GBLK - 1));    // column group 0..511
    const int c2 = gx * TPB + threadIdx.x;    // float2 column index (0..16383)
    const int ROW2 = B_COLS / 2;              // row stride in float2 units
    const int t_hi = (TM1 - 1) - RMAX * k;    // 1022 - 32k

    const float2* r = (const float2*)rewards + c2;
    const float2* v = (const float2*)values + c2;
    float2* o = (float2*)out + c2;

    // ---- local backward scan (carry-in = 0), 32 rows, batched LDG.64 ----
    float2 local[RMAX];
    float ax = 0.0f, ay = 0.0f;
    float2 vn = __ldcs(v + (t_hi + 1) * ROW2);

    if (k < NCHUNK - 1) {
        // Fast path: all rows valid, no predication.
        #pragma unroll
        for (int g0 = 0; g0 < RMAX; g0 += 8) {
            float2 rt[8], vt[8];
            #pragma unroll
            for (int i = 0; i < 8; ++i) {
                const int t = t_hi - (g0 + i);
                rt[i] = __ldcs(r + t * ROW2);
                vt[i] = __ldcs(v + t * ROW2);
            }
            #pragma unroll
            for (int i = 0; i < 8; ++i) {
                const float dx = fmaf(GAMMA, vn.x, rt[i].x) - vt[i].x;
                const float dy = fmaf(GAMMA, vn.y, rt[i].y) - vt[i].y;
                ax = fmaf(GL, ax, dx);
                ay = fmaf(GL, ay, dy);
                local[g0 + i] = make_float2(ax, ay);
                vn = vt[i];
            }
        }
        // publish chunk-sum C_k with epoch stamp
        *(float2*)&g_scratch[k * B_COLS + 2 * c2] = local[RMAX - 1];
        __threadfence();
        __syncwarp();
        if (threadIdx.x == 0) atomicExch(&g_flags[k * GBLK + gx], want);
    } else {
        // Last chunk (k=31): t goes 30..0; row index 31 invalid. No consumers.
        #pragma unroll
        for (int g0 = 0; g0 < RMAX; g0 += 8) {
            float2 rt[8], vt[8];
            #pragma unroll
            for (int i = 0; i < 8; ++i) {
                const int t = t_hi - (g0 + i);
                if (t >= 0) {
                    rt[i] = __ldcs(r + t * ROW2);
                    vt[i] = __ldcs(v + t * ROW2);
                } else {
                    rt[i] = make_float2(0.0f, 0.0f);
                    vt[i] = make_float2(0.0f, 0.0f);
                }
            }
            #pragma unroll
            for (int i = 0; i < 8; ++i) {
                const float dx = fmaf(GAMMA, vn.x, rt[i].x) - vt[i].x;
                const float dy = fmaf(GAMMA, vn.y, rt[i].y) - vt[i].y;
                ax = fmaf(GL, ax, dx);
                ay = fmaf(GL, ay, dy);
                local[g0 + i] = make_float2(ax, ay);
                vn = vt[i];
            }
        }
    }

    // ---- truncated lookback: A = sum_{j=k-1 .. k-d} C_j * gl^(32*(k-1-j)) ----
    float Ax = 0.0f, Ay = 0.0f;
    if (k > 0) {
        const int d = (k < DEPTH) ? k : DEPTH;
        if (threadIdx.x < (unsigned)d) {  // thread i waits on predecessor (k-1-i)
            unsigned int* fp = &g_flags[(k - 1 - (int)threadIdx.x) * GBLK + gx];
            while (atomicAdd(fp, 0u) < want) {}
        }
        __syncwarp();

        // gl^32 via 5 squarings
        const float g2 = GL * GL, g4 = g2 * g2, g8 = g4 * g4;
        const float g16 = g8 * g8, gl32 = g16 * g16;

        float w = 1.0f;
        for (int j = k - 1; j >= k - d; --j) {
            const float2 Cj = *(const float2*)&g_scratch[j * B_COLS + 2 * c2];
            Ax = fmaf(Cj.x, w, Ax);
            Ay = fmaf(Cj.y, w, Ay);
            w *= gl32;
        }
    }

    // ---- fixup + store: adv[t_hi - i] = local[i] + A * gl^(i+1) ----
    if (k < NCHUNK - 1) {
        #pragma unroll
        for (int i = 0; i < RMAX; ++i) {
            Ax *= GL;
            Ay *= GL;
            __stcs(o + (t_hi - i) * ROW2,
                   make_float2(local[i].x + Ax, local[i].y + Ay));
        }
    } else {
        #pragma unroll
        for (int i = 0; i < RMAX; ++i) {
            const int t = t_hi - i;
            Ax *= GL;
            Ay *= GL;
            if (t >= 0)
                __stcs(o + t * ROW2,
                       make_float2(local[i].x + Ax, local[i].y + Ay));
        }
    }
}

extern "C" void kernel_launch(void* const* d_in, const int* in_sizes, int n_in,
                              void* d_out, int out_size) {
    const float* rewards = (const float*)d_in[0];
    const float* values  = (const float*)d_in[1];
    float* out = (float*)d_out;

    gae_chunk_kernel<<<NBLK, TPB>>>(rewards, values, out);
}